// round 16
// baseline (speedup 1.0000x reference)
#include <cuda_runtime.h>
#include <cuda_fp16.h>
#include <math.h>
#include <stdint.h>

#define HDIM   1536
#define BB     4
#define SL     2048
#define NHEADS 12
#define HDH    128
#define MEMD   128
#define INNERD 6144
#define NT     (BB*SL)
#define KW     4
#define CHUNK  64
#define NCHUNK (SL/CHUNK)
#define MT     8
#define QS     129

// ------------------------------------------------------------------ scratch
__device__ float g_y   [(size_t)NT*HDIM];
__device__ float g_xh  [(size_t)NT*HDIM];
__device__ float g_big [(size_t)NT*2*HDIM];
__device__ float g_q   [(size_t)NT*4*HDH];
__device__ float g_k   [(size_t)NT*4*HDH];
__device__ float g_v   [(size_t)NT*4*HDH];
__device__ float g_rd  [(size_t)NT*4*HDH];
__device__ float g_mo  [(size_t)NT*4*HDH];
__device__ float g_gm  [(size_t)NT*4];
__device__ float g_hw  [(size_t)NT*NHEADS];
__device__ float g_gate[NT];
__device__ float g_wr  [4*65536];
__device__ __half g_hy  [(size_t)NT*HDIM];
__device__ __half g_ht0 [(size_t)NT*HDIM];
__device__ __half g_htc [(size_t)NT*HDIM];
__device__ __half g_ht1 [(size_t)NT*HDIM];
__device__ __half g_hffn[(size_t)NT*INNERD];
__device__ __half g_hbig[(size_t)NT*2*INNERD];
__device__ __half g_hwt [40108032];

__constant__ int c_dils[NHEADS][3] = {
    {1,2,4},{1,1,1},{4,8,16},{8,16,32},{32,64,128},{64,128,256},
    {256,512,1024},{1,100,200},{1,500,1000},{1,1024,2048},{3,9,27},{5,25,125}};

__device__ __forceinline__ float sigf(float v){ return 1.f/(1.f+expf(-v)); }
__device__ __forceinline__ float geluf(float v){ return 0.5f*v*(1.f+erff(v*0.70710678118654752f)); }
__device__ __forceinline__ float rtf(float v){
    float r; asm("cvt.rna.tf32.f32 %0, %1;" : "=f"(r) : "f"(v)); return r;
}
__device__ __forceinline__ uint32_t s2u(const void* p){
    uint32_t a;
    asm("{ .reg .u64 t; cvta.to.shared.u64 t, %1; cvt.u32.u64 %0, t; }" : "=r"(a) : "l"(p));
    return a;
}
__device__ __forceinline__ void cpa16(void* dst, const void* src){
    uint32_t d = s2u(dst);
    asm volatile("cp.async.cg.shared.global [%0], [%1], 16;" :: "r"(d), "l"(src) : "memory");
}
#define CPA_COMMIT() asm volatile("cp.async.commit_group;" ::: "memory")
#define CPA_WAIT2()  asm volatile("cp.async.wait_group 2;" ::: "memory")

__device__ __forceinline__ void mma8(float* c, const uint32_t* a, const uint32_t* b){
    asm volatile("mma.sync.aligned.m16n8k8.row.col.f32.tf32.tf32.f32 "
        "{%0,%1,%2,%3}, {%4,%5,%6,%7}, {%8,%9}, {%0,%1,%2,%3};"
        : "+f"(c[0]), "+f"(c[1]), "+f"(c[2]), "+f"(c[3])
        : "r"(a[0]), "r"(a[1]), "r"(a[2]), "r"(a[3]),
          "r"(b[0]), "r"(b[1]));
}
__device__ __forceinline__ void mma16h(float* c, const uint32_t* a, const uint32_t* b){
    asm volatile("mma.sync.aligned.m16n8k16.row.col.f32.f16.f16.f32 "
        "{%0,%1,%2,%3}, {%4,%5,%6,%7}, {%8,%9}, {%0,%1,%2,%3};"
        : "+f"(c[0]), "+f"(c[1]), "+f"(c[2]), "+f"(c[3])
        : "r"(a[0]), "r"(a[1]), "r"(a[2]), "r"(a[3]),
          "r"(b[0]), "r"(b[1]));
}

// ============================================================ fp16 big GEMM
// 128x128 CTA tile, 256 thr, warp tile 64x32, BK=32,
// 4-stage cp.async ring, single-sync mainloop, 2 CTAs/SM.
#define H2STRIDE 20
#define H2STAGE  (256*H2STRIDE)
// epi 0: acc(+bias)  epi 1: resid + gate[row]*(acc+bias)  epi 2: A*sig(acc+bias)
__global__ void __launch_bounds__(256,2)
mma_gemm_h(const __half* __restrict__ A, long lda,
           const __half* __restrict__ W, long ldw,
           void* __restrict__ Cv, long ldc,
           int K, int epi, int outH,
           const float* __restrict__ bias,
           const float* __restrict__ resid,
           const float* __restrict__ gate)
{
    extern __shared__ float gs[];
    uint32_t* su = (uint32_t*)gs;
    int tid = threadIdx.x, lane = tid & 31, warp = tid >> 5;
    int wm = warp & 1, wn = warp >> 1;
    int r = lane >> 2, cl = lane & 3;
    long bm = (long)blockIdx.y*128, bn = (long)blockIdx.x*128;

    float acc[4][4][4];
    #pragma unroll
    for (int i=0;i<4;i++)
        #pragma unroll
        for (int j=0;j<4;j++)
            #pragma unroll
            for (int q=0;q<4;q++) acc[i][j][q]=0.f;

    // 1024 16B chunks per stage: rows 0..127 = A, 128..255 = B
    const __half* src[4]; float* dst[4];
    #pragma unroll
    for (int p=0;p<4;p++){
        int q = tid + p*256;
        int row = q >> 2, c = q & 3;
        if (row < 128) src[p] = A + (bm + row)*lda + c*8;
        else           src[p] = W + (bn + row - 128)*ldw + c*8;
        dst[p] = gs + row*H2STRIDE + c*4;
    }
    const int iters = K >> 5;

    // prologue: stages 0,1,2
    #pragma unroll
    for (int s=0;s<3;s++){
        long k0 = (long)s*32;
        #pragma unroll
        for (int p=0;p<4;p++) cpa16(dst[p] + s*H2STAGE, src[p] + k0);
        CPA_COMMIT();
    }

    for (int i = 0; i < iters; i++){
        CPA_WAIT2();               // stage i&3 complete (<=2 newer groups in flight)
        __syncthreads();           // all warps done with stage (i-1)&3
        int nstage = i + 3;
        if (nstage < iters){       // prefetch into stage (i+3)&3 == (i-1)&3
            int sb = nstage & 3;
            long k0 = (long)nstage*32;
            #pragma unroll
            for (int p=0;p<4;p++) cpa16(dst[p] + sb*H2STAGE, src[p] + k0);
        }
        CPA_COMMIT();              // unconditional: keeps group accounting uniform
        int cs = i & 3;
        const uint32_t* Asm = su + cs*H2STAGE;
        const uint32_t* Bsm = Asm + 128*H2STRIDE;
        #pragma unroll
        for (int kk = 0; kk < 2; kk++){
            int kw = kk*8;
            uint32_t af[4][4], bf[4][2];
            #pragma unroll
            for (int mt=0;mt<4;mt++){
                int m0 = wm*64 + mt*16;
                af[mt][0] = Asm[(m0+r  )*H2STRIDE + kw + cl    ];
                af[mt][1] = Asm[(m0+r+8)*H2STRIDE + kw + cl    ];
                af[mt][2] = Asm[(m0+r  )*H2STRIDE + kw + cl + 4];
                af[mt][3] = Asm[(m0+r+8)*H2STRIDE + kw + cl + 4];
            }
            #pragma unroll
            for (int nt=0;nt<4;nt++){
                int n0 = wn*32 + nt*8;
                bf[nt][0] = Bsm[(n0+r)*H2STRIDE + kw + cl    ];
                bf[nt][1] = Bsm[(n0+r)*H2STRIDE + kw + cl + 4];
            }
            #pragma unroll
            for (int mt=0;mt<4;mt++)
                #pragma unroll
                for (int nt=0;nt<4;nt++)
                    mma16h(acc[mt][nt], af[mt], bf[nt]);
        }
    }

    #pragma unroll
    for (int mt=0;mt<4;mt++){
        #pragma unroll
        for (int nt=0;nt<4;nt++){
            long row0 = bm + wm*64 + mt*16 + r;
            long col  = bn + wn*32 + nt*8 + 2*cl;
            #pragma unroll
            for (int hh=0;hh<2;hh++){
                long row = row0 + hh*8;
                float v0 = acc[mt][nt][hh*2+0];
                float v1 = acc[mt][nt][hh*2+1];
                if (bias){ v0 += bias[col]; v1 += bias[col+1]; }
                if (epi == 1){
                    float g = gate[row];
                    v0 = resid[row*ldc + col]   + g*v0;
                    v1 = resid[row*ldc + col+1] + g*v1;
                } else if (epi == 2){
                    v0 = __half2float(A[row*lda + col])   * sigf(v0);
                    v1 = __half2float(A[row*lda + col+1]) * sigf(v1);
                }
                if (outH){
                    *(__half2*)((__half*)Cv + row*ldc + col) = __floats2half2_rn(v0, v1);
                } else {
                    float2 o; o.x = v0; o.y = v1;
                    *(float2*)((float*)Cv + row*ldc + col) = o;
                }
            }
        }
    }
}

// ============================================================ small tf32 GEMM core
__device__ __forceinline__ void small_gemm_body(
    const float* A, long lda, const float* W, long ldw,
    float* C, long ldc, int K, long bm)
{
    __shared__ float As[2][16][136];
    __shared__ float Bs[2][16][136];
    int tid = threadIdx.x, lane = tid & 31, warp = tid >> 5;
    int wm = warp & 1, wn = warp >> 1;
    int r = lane >> 2, cl = lane & 3;

    float acc[4][4][4];
    #pragma unroll
    for (int i=0;i<4;i++)
        #pragma unroll
        for (int j=0;j<4;j++)
            #pragma unroll
            for (int q=0;q<4;q++) acc[i][j][q]=0.f;

    int lm = tid & 127;
    int kq = tid >> 7;
    const float* Ab = A + (bm + lm)*lda + kq*4;
    const float* Wb = W + lm*ldw + kq*4;
    const int iters = K >> 4;
    {
        float4 a0 = *(const float4*)(Ab);
        float4 a1 = *(const float4*)(Ab + 8);
        float4 b0 = *(const float4*)(Wb);
        float4 b1 = *(const float4*)(Wb + 8);
        #pragma unroll
        for (int j=0;j<4;j++){
            As[0][kq*4+j][lm]   = ((const float*)&a0)[j];
            As[0][kq*4+8+j][lm] = ((const float*)&a1)[j];
            Bs[0][kq*4+j][lm]   = ((const float*)&b0)[j];
            Bs[0][kq*4+8+j][lm] = ((const float*)&b1)[j];
        }
    }
    __syncthreads();
    for (int i = 0; i < iters; i++){
        int bsel = i & 1;
        float4 a0, a1, b0, b1;
        if (i+1 < iters){
            const float* Ap = Ab + (long)(i+1)*16;
            const float* Wp = Wb + (long)(i+1)*16;
            a0 = *(const float4*)(Ap);  a1 = *(const float4*)(Ap + 8);
            b0 = *(const float4*)(Wp);  b1 = *(const float4*)(Wp + 8);
        }
        #pragma unroll
        for (int kk = 0; kk < 2; kk++){
            int kb = kk*8;
            uint32_t af[4][4], bf[4][2];
            #pragma unroll
            for (int mt=0;mt<4;mt++){
                int m0 = wm*64 + mt*16;
                af[mt][0] = __float_as_uint(As[bsel][kb+cl  ][m0+r  ]);
                af[mt][1] = __float_as_uint(As[bsel][kb+cl  ][m0+r+8]);
                af[mt][2] = __float_as_uint(As[bsel][kb+cl+4][m0+r  ]);
                af[mt][3] = __float_as_uint(As[bsel][kb+cl+4][m0+r+8]);
            }
            #pragma unroll
            for (int nt=0;nt<4;nt++){
                int n0 = wn*32 + nt*8;
                bf[nt][0] = __float_as_uint(Bs[bsel][kb+cl  ][n0+r]);
                bf[nt][1] = __float_as_uint(Bs[bsel][kb+cl+4][n0+r]);
            }
            #pragma unroll
            for (int mt=0;mt<4;mt++)
                #pragma unroll
                for (int nt=0;nt<4;nt++)
                    mma8(acc[mt][nt], af[mt], bf[nt]);
        }
        if (i+1 < iters){
            __syncthreads();
            int nb = (i+1)&1;
            #pragma unroll
            for (int j=0;j<4;j++){
                As[nb][kq*4+j][lm]   = ((const float*)&a0)[j];
                As[nb][kq*4+8+j][lm] = ((const float*)&a1)[j];
                Bs[nb][kq*4+j][lm]   = ((const float*)&b0)[j];
                Bs[nb][kq*4+8+j][lm] = ((const float*)&b1)[j];
            }
            __syncthreads();
        }
    }
    #pragma unroll
    for (int mt=0;mt<4;mt++){
        #pragma unroll
        for (int nt=0;nt<4;nt++){
            long row0 = bm + wm*64 + mt*16 + r;
            long col  = wn*32 + nt*8 + 2*cl;
            #pragma unroll
            for (int hh=0;hh<2;hh++){
                long row = row0 + hh*8;
                float2 o; o.x = acc[mt][nt][hh*2+0]; o.y = acc[mt][nt][hh*2+1];
                *(float2*)(C + row*ldc + col) = o;
            }
        }
    }
}
__global__ void __launch_bounds__(256)
mma_gemm_qkv(const float* __restrict__ A, long lda, long aZ,
             const float* __restrict__ Wbase,
             float* __restrict__ Q, float* __restrict__ Kb, float* __restrict__ V,
             int K)
{
    int which = blockIdx.z >> 2;
    int head  = blockIdx.z & 3;
    const float* W = Wbase + (size_t)which*65536 + (size_t)head*16384;
    float* C = (which == 0) ? Q : (which == 1) ? Kb : V;
    small_gemm_body(A + head*aZ, lda, W, 128, C + head*HDH, 512, K,
                    (long)blockIdx.y*128);
}
__global__ void __launch_bounds__(256)
mma_gemm_small(const float* __restrict__ A, long lda, long aZ,
               const float* __restrict__ W, long wZ,
               float* __restrict__ C, long cZ, int K)
{
    small_gemm_body(A + blockIdx.z*aZ, lda, W + blockIdx.z*wZ, 128,
                    C + blockIdx.z*cZ, 512, K, (long)blockIdx.y*128);
}

// ------------------------------------------------------------ weight conversion
__global__ void __launch_bounds__(256) cvtw_kernel(
    const float4* __restrict__ in, __half2* __restrict__ out, int n4)
{
    int stride = gridDim.x*256;
    for (int i = blockIdx.x*256 + threadIdx.x; i < n4; i += stride){
        float4 v = in[i];
        out[2*i]   = __floats2half2_rn(v.x, v.y);
        out[2*i+1] = __floats2half2_rn(v.z, v.w);
    }
}
__global__ void __launch_bounds__(256) roundw4_kernel(
    const float4* __restrict__ a, const float4* __restrict__ b,
    const float4* __restrict__ c, const float4* __restrict__ d,
    float4* __restrict__ out, int n4)
{
    int i = blockIdx.x*256 + threadIdx.x;
    if (i >= n4) return;
    const float4* src = (blockIdx.z == 0) ? a : (blockIdx.z == 1) ? b :
                        (blockIdx.z == 2) ? c : d;
    float4 v = src[i];
    v.x = rtf(v.x); v.y = rtf(v.y); v.z = rtf(v.z); v.w = rtf(v.w);
    out[(size_t)blockIdx.z*n4 + i] = v;
}

// ------------------------------------------------------------ rms + gate (+router)
__global__ void __launch_bounds__(256) rms_router_kernel(
    const float* __restrict__ x, const float* __restrict__ nw,
    const float* __restrict__ gw, const float* __restrict__ gb,
    float* __restrict__ y, __half* __restrict__ yh, float* __restrict__ gate,
    const float* __restrict__ rw, const float* __restrict__ rb,
    float* __restrict__ hw)
{
    __shared__ float sy[HDIM];
    __shared__ float wss[8], wgd[8];
    int t = blockIdx.x, tid = threadIdx.x;
    int lane = tid & 31, warp = tid >> 5;
    const float* xr = x + (size_t)t*HDIM;
    float ss = 0.f, gd = 0.f;
    for (int i = tid; i < HDIM; i += 256){
        float v = xr[i]; sy[i] = v; ss += v*v; gd += v*gw[i];
    }
    #pragma unroll
    for (int o = 16; o; o >>= 1){
        ss += __shfl_xor_sync(0xffffffffu, ss, o);
        gd += __shfl_xor_sync(0xffffffffu, gd, o);
    }
    if (lane == 0){ wss[warp] = ss; wgd[warp] = gd; }
    __syncthreads();
    float tot = wss[0]+wss[1]+wss[2]+wss[3]+wss[4]+wss[5]+wss[6]+wss[7];
    float rs = rsqrtf(tot*(1.f/HDIM) + 1e-6f);
    if (tid == 0){
        float tg = wgd[0]+wgd[1]+wgd[2]+wgd[3]+wgd[4]+wgd[5]+wgd[6]+wgd[7];
        gate[t] = sigf(tg + gb[0]);
    }
    for (int i = tid; i < HDIM; i += 256){
        float v = sy[i]*rs*nw[i];
        if (y)  y[(size_t)t*HDIM + i] = v;
        if (yh) yh[(size_t)t*HDIM + i] = __float2half_rn(v);
        sy[i] = v;
    }
    if (rw){
        __syncthreads();
        for (int r = warp; r < NHEADS; r += 8){
            float s = 0.f;
            for (int i = lane; i < HDIM; i += 32) s += sy[i]*rw[r*HDIM + i];
            #pragma unroll
            for (int o = 16; o; o >>= 1) s += __shfl_down_sync(0xffffffffu, s, o);
            if (lane == 0) hw[(size_t)t*NHEADS + r] = sigf(s + rb[r]);
        }
    }
}

// ------------------------------------------------------------ fused 6-stage conv stack
__global__ void __launch_bounds__(256) convfused_kernel(
    const float* __restrict__ in, __half* __restrict__ out,
    const float* __restrict__ w, const float* __restrict__ b)
{
    extern __shared__ float cs[];
    float* buf0 = cs;
    float* buf1 = cs + SL*8;
    int cg = blockIdx.x % (HDIM/8);
    int bb = blockIdx.x / (HDIM/8);
    int c0 = cg*8;
    int tid = threadIdx.x;
    const float* base = in + (size_t)bb*SL*HDIM + c0;
    for (int e = tid; e < SL*8; e += 256){
        int t = e >> 3, c = e & 7;
        buf0[e] = base[(size_t)t*HDIM + c];
    }
    __syncthreads();
    float* src = buf0; float* dst = buf1;
    int c = tid & 7;
    #pragma unroll
    for (int j = 0; j < 6; j++){
        int dil = 1 << j;
        float w0 = w[(j*HDIM + c0 + c)*KW + 0];
        float w1 = w[(j*HDIM + c0 + c)*KW + 1];
        float w2 = w[(j*HDIM + c0 + c)*KW + 2];
        float w3 = w[(j*HDIM + c0 + c)*KW + 3];
        float bj = b[j*HDIM + c0 + c];
        for (int t = tid >> 3; t < SL; t += 32){
            float xv = src[t*8 + c];
            float a = bj + xv*w3;
            int t1 = t - dil, t2 = t - 2*dil, t3 = t - 3*dil;
            if (t1 >= 0) a += src[t1*8 + c]*w2;
            if (t2 >= 0) a += src[t2*8 + c]*w1;
            if (t3 >= 0) a += src[t3*8 + c]*w0;
            dst[t*8 + c] = xv + geluf(a);
        }
        __syncthreads();
        float* tmp = src; src = dst; dst = tmp;
    }
    __half* obase = out + (size_t)bb*SL*HDIM + c0;
    for (int e = tid; e < SL*8; e += 256){
        int t = e >> 3, cc = e & 7;
        obase[(size_t)t*HDIM + cc] = __float2half_rn(src[e]);
    }
}

// ------------------------------------------------------------ fused head conv + mem add + router scale
__global__ void __launch_bounds__(256) headconv_fused(
    const float* __restrict__ xh, const float* __restrict__ mo,
    const float* __restrict__ hwv,
    const float* __restrict__ w, const float* __restrict__ b,
    __half* __restrict__ out)
{
    extern __shared__ float cs[];
    float* buf0 = cs;
    float* buf1 = cs + SL*4;
    int g4   = blockIdx.x & 31;
    int head = (blockIdx.x >> 5) % NHEADS;
    int bb   = blockIdx.x / (32*NHEADS);
    int tid = threadIdx.x;
    int c = tid & 3;
    int ch0 = head*HDH + g4*4;
    const float* base = xh + (size_t)bb*SL*HDIM + ch0;
    for (int e = tid; e < SL*4; e += 256){
        int t = e >> 2, cc = e & 3;
        buf0[e] = base[(size_t)t*HDIM + cc];
    }
    __syncthreads();
    float* src = buf0; float* dst = buf1;
    #pragma unroll
    for (int j = 0; j < 3; j++){
        int dil = c_dils[head][j];
        int d = g4*4 + c;
        const float* wp = w + ((head*3 + j)*HDH + d)*KW;
        float w0 = wp[0], w1 = wp[1], w2 = wp[2], w3 = wp[3];
        float bj = b[(head*3 + j)*HDH + d];
        for (int t = tid >> 2; t < SL; t += 64){
            float xv = src[t*4 + c];
            float a = bj + xv*w3;
            int t1 = t - dil, t2 = t - 2*dil, t3 = t - 3*dil;
            if (t1 >= 0) a += src[t1*4 + c]*w2;
            if (t2 >= 0) a += src[t2*4 + c]*w1;
            if (t3 >= 0) a += src[t3*4 + c]*w0;
            dst[t*4 + c] = xv + a;
        }
        __syncthreads();
        float* tmp = src; src = dst; dst = tmp;
    }
    __half* obase = out + (size_t)bb*SL*HDIM + ch0;
    bool memh = (head >= 6 && head <= 9);
    for (int e = tid; e < SL*4; e += 256){
        int t = e >> 2, cc = e & 3;
        long tok = (long)bb*SL + t;
        float v = src[e];
        if (memh) v += mo[(tok*4 + (head-6))*HDH + g4*4 + cc];
        obase[(size_t)t*HDIM + cc] = __float2half_rn(v * hwv[tok*NHEADS + head]);
    }
}

// ------------------------------------------------------------ GLU + memgate fused
__global__ void __launch_bounds__(256) glu_gate_kernel(
    const float4* __restrict__ big, float4* __restrict__ xh,
    const float* __restrict__ wg, const float* __restrict__ bg,
    float* __restrict__ gm)
{
    __shared__ float red[8][4];
    int t = blockIdx.x, tid = threadIdx.x;
    int lane = tid & 31, warp = tid >> 5;
    const float4* crow = big + (size_t)t*(2*HDIM/4);
    const float4* grow = crow + HDIM/4;
    float4* orow = xh + (size_t)t*(HDIM/4);
    float acc0=0.f, acc1=0.f, acc2=0.f, acc3=0.f;
    for (int i = tid; i < HDIM/4; i += 256){
        float4 c = crow[i];
        float4 g = grow[i];
        float4 o;
        o.x = rtf(c.x*sigf(g.x)); o.y = rtf(c.y*sigf(g.y));
        o.z = rtf(c.z*sigf(g.z)); o.w = rtf(c.w*sigf(g.w));
        orow[i] = o;
        int ch = i*4;
        if (ch >= 6*HDH && ch < 10*HDH){
            int h = (ch - 6*HDH) >> 7;
            int d = (ch - 6*HDH) & 127;
            const float* wp = wg + h*HDH + d;
            float s = o.x*wp[0] + o.y*wp[1] + o.z*wp[2] + o.w*wp[3];
            if (h == 0) acc0 += s; else if (h == 1) acc1 += s;
            else if (h == 2) acc2 += s; else acc3 += s;
        }
    }
    #pragma unroll
    for (int o = 16; o; o >>= 1){
        acc0 += __shfl_xor_sync(0xffffffffu, acc0, o);
        acc1 += __shfl_xor_sync(0xffffffffu, acc1, o);
        acc2 += __shfl_xor_sync(0xffffffffu, acc2, o);
        acc3 += __shfl_xor_sync(0xffffffffu, acc3, o);
    }
    if (lane == 0){
        red[warp][0] = acc0; red[warp][1] = acc1;
        red[warp][2] = acc2; red[warp][3] = acc3;
    }
    __syncthreads();
    if (tid < 4){
        float s = 0.f;
        #pragma unroll
        for (int w2 = 0; w2 < 8; w2++) s += red[w2][tid];
        gm[t*4 + tid] = sigf(s + bg[tid]);
    }
}

// ------------------------------------------------------------ fp16 GLU (FFN)
__global__ void __launch_bounds__(256) glu_h8(
    const uint4* __restrict__ big, uint4* __restrict__ out, int N8)
{
    long idx = (long)blockIdx.x*256 + threadIdx.x;
    if (idx >= (long)NT*N8) return;
    long m = idx / N8; int n = (int)(idx % N8);
    uint4 cu = big[m*2*N8 + n];
    uint4 gu = big[m*2*N8 + N8 + n];
    uint4 ou;
    uint32_t* cp = (uint32_t*)&cu;
    uint32_t* gp = (uint32_t*)&gu;
    uint32_t* op = (uint32_t*)&ou;
    #pragma unroll
    for (int j = 0; j < 4; j++){
        float2 cf = __half22float2(*(__half2*)&cp[j]);
        float2 gf = __half22float2(*(__half2*)&gp[j]);
        __half2 r = __floats2half2_rn(cf.x*sigf(gf.x), cf.y*sigf(gf.y));
        op[j] = *(uint32_t*)&r;
    }
    out[idx] = ou;
}

// ------------------------------------------------------------ memory scan
#define SCAN_SMEM ((64*QS*2 + 64*MT + 64 + 128*(MT+1) + 4)*4)
__global__ void __launch_bounds__(256) memscan_kernel(
    const float* __restrict__ q, const float* __restrict__ k,
    const float* __restrict__ v, const float* __restrict__ g,
    float* __restrict__ reads)
{
    extern __shared__ float smem[];
    float* sQ  = smem;
    float* sK  = sQ + 64*QS;
    float* sV  = sK + 64*QS;
    float* sG  = sV + 64*MT;
    float* sM  = sG + 64;
    float* sDec= sM + 128*(MT+1);
    int tid  = threadIdx.x;
    int mblk = blockIdx.x & 15;
    int h    = (blockIdx.x >> 4) & 3;
    int b    = blockIdx.x >> 6;
    int m0   = mblk * MT;
    for (int i = tid; i < 128*(MT+1); i += 256) sM[i] = 0.f;
    for (int c = 0; c < NCHUNK; c++){
        int tok0 = b*SL + c*CHUNK;
        __syncthreads();
        if (tid < 64) sG[tid] = g[(tok0 + tid)*4 + h];
        __syncthreads();
        #pragma unroll
        for (int it = 0; it < 8; it++){
            int li = tid + it*256;
            int s  = li >> 5;
            int e4 = (li & 31) << 2;
            size_t gi = ((size_t)(tok0 + s)*4 + h)*HDH + e4;
            float4 qa = *(const float4*)(q + gi);
            float4 ka = *(const float4*)(k + gi);
            float gs = sG[s];
            int so = s*QS + e4;
            sQ[so] = qa.x; sQ[so+1] = qa.y; sQ[so+2] = qa.z; sQ[so+3] = qa.w;
            sK[so] = ka.x*gs; sK[so+1] = ka.y*gs; sK[so+2] = ka.z*gs; sK[so+3] = ka.w*gs;
        }
        if (tid < 128){
            int s = tid >> 1; int mm = (tid & 1)*4;
            float4 va = *(const float4*)(v + ((size_t)(tok0 + s)*4 + h)*HDH + m0 + mm);
            float* dv = &sV[s*MT + mm];
            dv[0]=va.x; dv[1]=va.y; dv[2]=va.z; dv[3]=va.w;
        }
        __syncthreads();
        if (tid < 32){
            float dsum = sG[tid] + sG[tid + 32];
            #pragma unroll
            for (int o = 16; o; o >>= 1) dsum += __shfl_down_sync(0xffffffffu, dsum, o);
            if (tid == 0) sDec[0] = 1.f - dsum*(1.f/64.f);
        }
        {
            int s  = tid & 63;
            int mi = (tid >> 6)*2;
            float a0 = 0.f, a1 = 0.f;
            const float* qr = sQ + s*QS;
            #pragma unroll 8
            for (int d = 0; d < HDH; d++){
                float qv = qr[d];
                a0 += qv * sM[d*(MT+1) + mi];
                a1 += qv * sM[d*(MT+1) + mi + 1];
            }
            size_t ro = ((size_t)(tok0 + s)*4 + h)*HDH + m0 + mi;
            reads[ro] = rtf(a0); reads[ro+1] = rtf(a1);
        }
        __syncthreads();
        {
            int d  = tid & 127;
            int mb = (tid >> 7)*4;
            float dec = sDec[0];
            float a0 = dec*sM[d*(MT+1)+mb+0];
            float a1 = dec*sM[d*(MT+1)+mb+1];
            float a2 = dec*sM[d*(MT+1)+mb+2];
            float a3 = dec*sM[d*(MT+1)+mb+3];
            #pragma unroll 8
            for (int s = 0; s < 64; s++){
                float kgv = sK[s*QS + d];
                const float* vr = sV + s*MT + mb;
                a0 += kgv*vr[0]; a1 += kgv*vr[1]; a2 += kgv*vr[2]; a3 += kgv*vr[3];
            }
            sM[d*(MT+1)+mb+0]=a0; sM[d*(MT+1)+mb+1]=a1;
            sM[d*(MT+1)+mb+2]=a2; sM[d*(MT+1)+mb+3]=a3;
        }
    }
}

// ------------------------------------------------------------ host side
template<typename T>
static T* F(const void* sym){
    void* p = nullptr;
    cudaGetSymbolAddress(&p, sym);
    return (T*)p;
}

#define GEMMH_SMEM (4*H2STAGE*4)
#define CONV_SMEM  (2*SL*8*4)
#define HC_SMEM    (2*SL*4*4)

static void gemmH(const __half* A, const __half* W, void* C,
                  long lda, long ldw, long ldc, int M, int N, int K,
                  int epi, int outH, const float* bias,
                  const float* resid, const float* gate)
{
    dim3 g(N/128, M/128, 1);
    mma_gemm_h<<<g, 256, GEMMH_SMEM>>>(A, lda, W, ldw, C, ldc,
                                       K, epi, outH, bias, resid, gate);
}
static void cvtwS(const float* in, __half* out, size_t n, cudaStream_t st){
    int n4 = (int)(n/4);
    int grid = (n4/4 + 255)/256;
    if (grid < 1) grid = 1;
    cvtw_kernel<<<grid, 256, 0, st>>>((const float4*)in, (__half2*)out, n4);
}

extern "C" void kernel_launch(void* const* d_in, const int* in_sizes, int n_in,
                              void* d_out, int out_size)
{
    const float* x            = (const float*)d_in[0];
    const float* norm1_w      = (const float*)d_in[1];
    const float* norm2_w      = (const float*)d_in[2];
    const float* norm3_w      = (const float*)d_in[3];
    const float* convstack_w  = (const float*)d_in[4];
    const float* convstack_b  = (const float*)d_in[5];
    const float* conv_proj_w  = (const float*)d_in[6];
    const float* conv_proj_b  = (const float*)d_in[7];
    const float* gate_proj_w  = (const float*)d_in[8];
    const float* head_router_w= (const float*)d_in[9];
    const float* head_router_b= (const float*)d_in[10];
    const float* head_conv_w  = (const float*)d_in[11];
    const float* head_conv_b  = (const float*)d_in[12];
    const float* mem_Wq       = (const float*)d_in[13];
    const float* mem_Wk       = (const float*)d_in[14];
    const float* mem_Wv       = (const float*)d_in[15];
    const float* mem_Wg_w     = (const float*)d_in[16];
    const float* mem_Wg_b     = (const float*)d_in[17];
    const float* mem_Wout     = (const float*)d_in[18];
    const float* mix_gate_w   = (const float*)d_in[19];
    const float* mix_gate_b   = (const float*)d_in[20];
    const float* mixing_w     = (const float*)d_in[21];
    const float* mixing_b     = (const float*)d_in[22];
    const float* ffn_in_w     = (const float*)d_in[23];
    const float* ffn_out_w    = (const float*)d_in[24];
    const float* conv_gate_w  = (const float*)d_in[25];
    const float* conv_gate_b  = (const float*)d_in[26];
    const float* state_gate_w = (const float*)d_in[27];
    const float* state_gate_b = (const float*)d_in[28];
    const float* ffn_gate_w   = (const float*)d_in[29];
    const float* ffn_gate_b   = (const float*)d_in[30];
    float* out = (float*)d_out;

    float*  y    = F<float>(g_y);
    float*  xh   = F<float>(g_xh);
    float*  big  = F<float>(g_big);
    float*  qb   = F<float>(g_q);
    float*  kb   = F<float>(g_k);
    float*  vb   = F<float>(g_v);
    float*  rd   = F<float>(g_rd);
    float*  mo   = F<float>(g_mo);
    float*  gm   = F<float>(g_gm);
    float*  hw   = F<float>(g_hw);
    float*  gate = F<float>(g_gate);
    float*  wr   = F<float>(g_wr);
    __half* hy   = F<__half>(g_hy);
    __half* ht0  = F<__half>(g_ht0);
    __half* htc  = F<__half>(g_htc);
    __half* ht1  = F<__half>(g_ht1);
    __half* hffn = F<__half>(g_hffn);
    __half* hbig = F<__half>(g_hbig);
    __half* hwt  = F<__half>(g_hwt);

    __half* hw_cp = hwt;                // conv_proj  2359296
    __half* hw_gp = hwt + 2359296;      // gate_proj  4718592
    __half* hw_mg = hwt + 7077888;      // mix_gate   2359296
    __half* hw_mx = hwt + 9437184;      // mixing     2359296
    __half* hw_fi = hwt + 11796480;     // ffn_in    18874368
    __half* hw_fo = hwt + 30670848;     // ffn_out    9437184
    float* w_q = wr;                    // [wq|wk|wv|wo] each 65536

    cudaFuncSetAttribute(memscan_kernel,
        cudaFuncAttributeMaxDynamicSharedMemorySize, SCAN_SMEM);
    cudaFuncSetAttribute(mma_gemm_h,
        cudaFuncAttributeMaxDynamicSharedMemorySize, GEMMH_SMEM);
    cudaFuncSetAttribute(convfused_kernel,
        cudaFuncAttributeMaxDynamicSharedMemorySize, CONV_SMEM);
    cudaFuncSetAttribute(headconv_fused,
        cudaFuncAttributeMaxDynamicSharedMemorySize, HC_SMEM);

    static cudaStream_t s2 = nullptr;
    static cudaEvent_t evF = nullptr, evJ = nullptr;
    if (!s2){
        cudaStreamCreateWithFlags(&s2, cudaStreamNonBlocking);
        cudaEventCreateWithFlags(&evF, cudaEventDisableTiming);
        cudaEventCreateWithFlags(&evJ, cudaEventDisableTiming);
    }

    // fork: weight prep for stages B/C overlaps stage A
    cudaEventRecord(evF, 0);
    cudaStreamWaitEvent(s2, evF, 0);
    cvtwS(gate_proj_w, hw_gp, 4718592, s2);
    cvtwS(mix_gate_w,  hw_mg, 2359296, s2);
    cvtwS(mixing_w,  hw_mx, 2359296, s2);
    cvtwS(ffn_in_w,  hw_fi, 18874368, s2);
    cvtwS(ffn_out_w, hw_fo, 9437184, s2);
    roundw4_kernel<<<dim3(64,1,4), 256, 0, s2>>>(
        (const float4*)mem_Wq, (const float4*)mem_Wk,
        (const float4*)mem_Wv, (const float4*)mem_Wout,
        (float4*)w_q, 16384);
    cudaEventRecord(evJ, s2);

    // ============ stage A ============
    cvtwS(conv_proj_w, hw_cp, 2359296, 0);
    rms_router_kernel<<<NT,256>>>(x, norm1_w, conv_gate_w, conv_gate_b,
                                  y, nullptr, gate, nullptr, nullptr, nullptr);
    convfused_kernel<<<BB*(HDIM/8), 256, CONV_SMEM>>>(y, ht0,
                                  convstack_w, convstack_b);
    gemmH(ht0, hw_cp, out, HDIM, HDIM, HDIM, NT, HDIM, HDIM, 1, 0,
          conv_proj_b, x, gate);

    cudaStreamWaitEvent(0, evJ, 0);

    // ============ stage B: state branch ============
    rms_router_kernel<<<NT,256>>>(out, norm2_w, state_gate_w, state_gate_b,
                                  nullptr, hy, gate, head_router_w, head_router_b, hw);
    gemmH(hy, hw_gp, big, HDIM, HDIM, 2*HDIM, NT, 2*HDIM, HDIM, 0, 0,
          nullptr, nullptr, nullptr);
    glu_gate_kernel<<<NT,256>>>((const float4*)big, (float4*)xh,
                                mem_Wg_w, mem_Wg_b, gm);
    {
        dim3 g(1, NT/128, 12);
        mma_gemm_qkv<<<g, 256>>>(xh + 6*HDH, HDIM, HDH, w_q, qb, kb, vb, 128);
    }
    memscan_kernel<<<BB*4*(MEMD/MT), 256, SCAN_SMEM>>>(qb, kb, vb, gm, rd);
    {
        dim3 g(1, NT/128, 4);
        mma_gemm_small<<<g, 256>>>(rd, 512, HDH, w_q + 196608, 16384, mo, HDH, 128);
    }
    headconv_fused<<<BB*NHEADS*32, 256, HC_SMEM>>>(xh, mo, hw,
                                  head_conv_w, head_conv_b, htc);
    gemmH(htc, hw_mg, ht1, HDIM, HDIM, HDIM, NT, HDIM, HDIM, 2, 1,
          mix_gate_b, nullptr, nullptr);
    gemmH(ht1, hw_mx, out, HDIM, HDIM, HDIM, NT, HDIM, HDIM, 1, 0,
          mixing_b, out, gate);

    // ============ stage C: FFN ============
    rms_router_kernel<<<NT,256>>>(out, norm3_w, ffn_gate_w, ffn_gate_b,
                                  nullptr, hy, gate, nullptr, nullptr, nullptr);
    gemmH(hy, hw_fi, hbig, HDIM, HDIM, 2*INNERD, NT, 2*INNERD, HDIM, 0, 1,
          nullptr, nullptr, nullptr);
    glu_h8<<<(NT*(INNERD/8) + 255)/256, 256>>>((const uint4*)hbig, (uint4*)hffn, INNERD/8);
    gemmH(hffn, hw_fo, out, INNERD, INNERD, HDIM, NT, HDIM, INNERD, 1, 0,
          nullptr, out, gate);
}

// round 17
// speedup vs baseline: 1.0284x; 1.0284x over previous
#include <cuda_runtime.h>
#include <cuda_fp16.h>
#include <math.h>
#include <stdint.h>

#define HDIM   1536
#define BB     4
#define SL     2048
#define NHEADS 12
#define HDH    128
#define MEMD   128
#define INNERD 6144
#define NT     (BB*SL)
#define KW     4
#define CHUNK  64
#define NCHUNK (SL/CHUNK)
#define MT     8
#define QS     129

// ------------------------------------------------------------------ scratch
__device__ float g_y   [(size_t)NT*HDIM];
__device__ float g_xh  [(size_t)NT*HDIM];
__device__ float g_q   [(size_t)NT*4*HDH];
__device__ float g_k   [(size_t)NT*4*HDH];
__device__ float g_v   [(size_t)NT*4*HDH];
__device__ float g_rd  [(size_t)NT*4*HDH];
__device__ float g_mo  [(size_t)NT*4*HDH];
__device__ float g_gm  [(size_t)NT*4];
__device__ float g_hw  [(size_t)NT*NHEADS];
__device__ float g_gate[NT];
__device__ float g_wr  [4*65536];
__device__ __half g_hy  [(size_t)NT*HDIM];
__device__ __half g_ht0 [(size_t)NT*HDIM];
__device__ __half g_htc [(size_t)NT*HDIM];
__device__ __half g_ht1 [(size_t)NT*HDIM];
__device__ __half g_hffn[(size_t)NT*INNERD];
__device__ __half g_hbig[(size_t)NT*2*INNERD];
__device__ __half g_hwt [40108032];

__constant__ int c_dils[NHEADS][3] = {
    {1,2,4},{1,1,1},{4,8,16},{8,16,32},{32,64,128},{64,128,256},
    {256,512,1024},{1,100,200},{1,500,1000},{1,1024,2048},{3,9,27},{5,25,125}};

__device__ __forceinline__ float sigf(float v){ return 1.f/(1.f+expf(-v)); }
__device__ __forceinline__ float geluf(float v){ return 0.5f*v*(1.f+erff(v*0.70710678118654752f)); }
__device__ __forceinline__ float rtf(float v){
    float r; asm("cvt.rna.tf32.f32 %0, %1;" : "=f"(r) : "f"(v)); return r;
}
__device__ __forceinline__ uint32_t s2u(const void* p){
    uint32_t a;
    asm("{ .reg .u64 t; cvta.to.shared.u64 t, %1; cvt.u32.u64 %0, t; }" : "=r"(a) : "l"(p));
    return a;
}
__device__ __forceinline__ void cpa16(void* dst, const void* src){
    uint32_t d = s2u(dst);
    asm volatile("cp.async.cg.shared.global [%0], [%1], 16;" :: "r"(d), "l"(src) : "memory");
}
#define CPA_COMMIT() asm volatile("cp.async.commit_group;" ::: "memory")
#define CPA_WAIT2()  asm volatile("cp.async.wait_group 2;" ::: "memory")

__device__ __forceinline__ void mma8(float* c, const uint32_t* a, const uint32_t* b){
    asm volatile("mma.sync.aligned.m16n8k8.row.col.f32.tf32.tf32.f32 "
        "{%0,%1,%2,%3}, {%4,%5,%6,%7}, {%8,%9}, {%0,%1,%2,%3};"
        : "+f"(c[0]), "+f"(c[1]), "+f"(c[2]), "+f"(c[3])
        : "r"(a[0]), "r"(a[1]), "r"(a[2]), "r"(a[3]),
          "r"(b[0]), "r"(b[1]));
}
__device__ __forceinline__ void mma16h(float* c, const uint32_t* a, const uint32_t* b){
    asm volatile("mma.sync.aligned.m16n8k16.row.col.f32.f16.f16.f32 "
        "{%0,%1,%2,%3}, {%4,%5,%6,%7}, {%8,%9}, {%0,%1,%2,%3};"
        : "+f"(c[0]), "+f"(c[1]), "+f"(c[2]), "+f"(c[3])
        : "r"(a[0]), "r"(a[1]), "r"(a[2]), "r"(a[3]),
          "r"(b[0]), "r"(b[1]));
}

// ============================================================ fp16 big GEMM (R15: 128x128 tile, 3-stage, 2 CTAs/SM)
#define H2STRIDE 20
#define H2STAGE  (256*H2STRIDE)
// epi 0: acc(+bias)  epi 1: resid + gate[row]*(acc+bias)  epi 2: A*sig(acc+bias)
__global__ void __launch_bounds__(256,2)
mma_gemm_h(const __half* __restrict__ A, long lda,
           const __half* __restrict__ W, long ldw,
           void* __restrict__ Cv, long ldc,
           int K, int epi, int outH,
           const float* __restrict__ bias,
           const float* __restrict__ resid,
           const float* __restrict__ gate)
{
    extern __shared__ float gs[];
    uint32_t* su = (uint32_t*)gs;
    int tid = threadIdx.x, lane = tid & 31, warp = tid >> 5;
    int wm = warp & 1, wn = warp >> 1;
    int r = lane >> 2, cl = lane & 3;
    long bm = (long)blockIdx.y*128, bn = (long)blockIdx.x*128;

    float acc[4][4][4];
    #pragma unroll
    for (int i=0;i<4;i++)
        #pragma unroll
        for (int j=0;j<4;j++)
            #pragma unroll
            for (int q=0;q<4;q++) acc[i][j][q]=0.f;

    const __half* src[4]; float* dst[4];
    #pragma unroll
    for (int p=0;p<4;p++){
        int q = tid + p*256;
        int row = q >> 2, c = q & 3;
        if (row < 128) src[p] = A + (bm + row)*lda + c*8;
        else           src[p] = W + (bn + row - 128)*ldw + c*8;
        dst[p] = gs + row*H2STRIDE + c*4;
    }
    const int iters = K >> 5;

    #pragma unroll
    for (int s=0;s<2;s++){
        long k0 = (long)s*32;
        #pragma unroll
        for (int p=0;p<4;p++) cpa16(dst[p] + s*H2STAGE, src[p] + k0);
        CPA_COMMIT();
    }

    for (int i = 0; i < iters; i++){
        int nstage = i + 2;
        if (nstage < iters){
            int sb = nstage - (nstage/3)*3;
            long k0 = (long)nstage*32;
            #pragma unroll
            for (int p=0;p<4;p++) cpa16(dst[p] + sb*H2STAGE, src[p] + k0);
        }
        CPA_COMMIT();
        CPA_WAIT2();
        __syncthreads();
        int cs = i - (i/3)*3;
        const uint32_t* Asm = su + cs*H2STAGE;
        const uint32_t* Bsm = Asm + 128*H2STRIDE;
        #pragma unroll
        for (int kk = 0; kk < 2; kk++){
            int kw = kk*8;
            uint32_t af[4][4], bf[4][2];
            #pragma unroll
            for (int mt=0;mt<4;mt++){
                int m0 = wm*64 + mt*16;
                af[mt][0] = Asm[(m0+r  )*H2STRIDE + kw + cl    ];
                af[mt][1] = Asm[(m0+r+8)*H2STRIDE + kw + cl    ];
                af[mt][2] = Asm[(m0+r  )*H2STRIDE + kw + cl + 4];
                af[mt][3] = Asm[(m0+r+8)*H2STRIDE + kw + cl + 4];
            }
            #pragma unroll
            for (int nt=0;nt<4;nt++){
                int n0 = wn*32 + nt*8;
                bf[nt][0] = Bsm[(n0+r)*H2STRIDE + kw + cl    ];
                bf[nt][1] = Bsm[(n0+r)*H2STRIDE + kw + cl + 4];
            }
            #pragma unroll
            for (int mt=0;mt<4;mt++)
                #pragma unroll
                for (int nt=0;nt<4;nt++)
                    mma16h(acc[mt][nt], af[mt], bf[nt]);
        }
        __syncthreads();
    }

    #pragma unroll
    for (int mt=0;mt<4;mt++){
        #pragma unroll
        for (int nt=0;nt<4;nt++){
            long row0 = bm + wm*64 + mt*16 + r;
            long col  = bn + wn*32 + nt*8 + 2*cl;
            #pragma unroll
            for (int hh=0;hh<2;hh++){
                long row = row0 + hh*8;
                float v0 = acc[mt][nt][hh*2+0];
                float v1 = acc[mt][nt][hh*2+1];
                if (bias){ v0 += bias[col]; v1 += bias[col+1]; }
                if (epi == 1){
                    float g = gate[row];
                    v0 = resid[row*ldc + col]   + g*v0;
                    v1 = resid[row*ldc + col+1] + g*v1;
                } else if (epi == 2){
                    v0 = __half2float(A[row*lda + col])   * sigf(v0);
                    v1 = __half2float(A[row*lda + col+1]) * sigf(v1);
                }
                if (outH){
                    *(__half2*)((__half*)Cv + row*ldc + col) = __floats2half2_rn(v0, v1);
                } else {
                    float2 o; o.x = v0; o.y = v1;
                    *(float2*)((float*)Cv + row*ldc + col) = o;
                }
            }
        }
    }
}

// ============================================================ small tf32 GEMM core
__device__ __forceinline__ void small_gemm_body(
    const float* A, long lda, const float* W, long ldw,
    float* C, long ldc, int K, long bm)
{
    __shared__ float As[2][16][136];
    __shared__ float Bs[2][16][136];
    int tid = threadIdx.x, lane = tid & 31, warp = tid >> 5;
    int wm = warp & 1, wn = warp >> 1;
    int r = lane >> 2, cl = lane & 3;

    float acc[4][4][4];
    #pragma unroll
    for (int i=0;i<4;i++)
        #pragma unroll
        for (int j=0;j<4;j++)
            #pragma unroll
            for (int q=0;q<4;q++) acc[i][j][q]=0.f;

    int lm = tid & 127;
    int kq = tid >> 7;
    const float* Ab = A + (bm + lm)*lda + kq*4;
    const float* Wb = W + lm*ldw + kq*4;
    const int iters = K >> 4;
    {
        float4 a0 = *(const float4*)(Ab);
        float4 a1 = *(const float4*)(Ab + 8);
        float4 b0 = *(const float4*)(Wb);
        float4 b1 = *(const float4*)(Wb + 8);
        #pragma unroll
        for (int j=0;j<4;j++){
            As[0][kq*4+j][lm]   = ((const float*)&a0)[j];
            As[0][kq*4+8+j][lm] = ((const float*)&a1)[j];
            Bs[0][kq*4+j][lm]   = ((const float*)&b0)[j];
            Bs[0][kq*4+8+j][lm] = ((const float*)&b1)[j];
        }
    }
    __syncthreads();
    for (int i = 0; i < iters; i++){
        int bsel = i & 1;
        float4 a0, a1, b0, b1;
        if (i+1 < iters){
            const float* Ap = Ab + (long)(i+1)*16;
            const float* Wp = Wb + (long)(i+1)*16;
            a0 = *(const float4*)(Ap);  a1 = *(const float4*)(Ap + 8);
            b0 = *(const float4*)(Wp);  b1 = *(const float4*)(Wp + 8);
        }
        #pragma unroll
        for (int kk = 0; kk < 2; kk++){
            int kb = kk*8;
            uint32_t af[4][4], bf[4][2];
            #pragma unroll
            for (int mt=0;mt<4;mt++){
                int m0 = wm*64 + mt*16;
                af[mt][0] = __float_as_uint(As[bsel][kb+cl  ][m0+r  ]);
                af[mt][1] = __float_as_uint(As[bsel][kb+cl  ][m0+r+8]);
                af[mt][2] = __float_as_uint(As[bsel][kb+cl+4][m0+r  ]);
                af[mt][3] = __float_as_uint(As[bsel][kb+cl+4][m0+r+8]);
            }
            #pragma unroll
            for (int nt=0;nt<4;nt++){
                int n0 = wn*32 + nt*8;
                bf[nt][0] = __float_as_uint(Bs[bsel][kb+cl  ][n0+r]);
                bf[nt][1] = __float_as_uint(Bs[bsel][kb+cl+4][n0+r]);
            }
            #pragma unroll
            for (int mt=0;mt<4;mt++)
                #pragma unroll
                for (int nt=0;nt<4;nt++)
                    mma8(acc[mt][nt], af[mt], bf[nt]);
        }
        if (i+1 < iters){
            __syncthreads();
            int nb = (i+1)&1;
            #pragma unroll
            for (int j=0;j<4;j++){
                As[nb][kq*4+j][lm]   = ((const float*)&a0)[j];
                As[nb][kq*4+8+j][lm] = ((const float*)&a1)[j];
                Bs[nb][kq*4+j][lm]   = ((const float*)&b0)[j];
                Bs[nb][kq*4+8+j][lm] = ((const float*)&b1)[j];
            }
            __syncthreads();
        }
    }
    #pragma unroll
    for (int mt=0;mt<4;mt++){
        #pragma unroll
        for (int nt=0;nt<4;nt++){
            long row0 = bm + wm*64 + mt*16 + r;
            long col  = wn*32 + nt*8 + 2*cl;
            #pragma unroll
            for (int hh=0;hh<2;hh++){
                long row = row0 + hh*8;
                float2 o; o.x = acc[mt][nt][hh*2+0]; o.y = acc[mt][nt][hh*2+1];
                *(float2*)(C + row*ldc + col) = o;
            }
        }
    }
}
__global__ void __launch_bounds__(256)
mma_gemm_qkv(const float* __restrict__ A, long lda, long aZ,
             const float* __restrict__ Wbase,
             float* __restrict__ Q, float* __restrict__ Kb, float* __restrict__ V,
             int K)
{
    int which = blockIdx.z >> 2;
    int head  = blockIdx.z & 3;
    const float* W = Wbase + (size_t)which*65536 + (size_t)head*16384;
    float* C = (which == 0) ? Q : (which == 1) ? Kb : V;
    small_gemm_body(A + head*aZ, lda, W, 128, C + head*HDH, 512, K,
                    (long)blockIdx.y*128);
}
__global__ void __launch_bounds__(256)
mma_gemm_small(const float* __restrict__ A, long lda, long aZ,
               const float* __restrict__ W, long wZ,
               float* __restrict__ C, long cZ, int K)
{
    small_gemm_body(A + blockIdx.z*aZ, lda, W + blockIdx.z*wZ, 128,
                    C + blockIdx.z*cZ, 512, K, (long)blockIdx.y*128);
}

// ------------------------------------------------------------ weight conversion
__global__ void __launch_bounds__(256) cvtw_kernel(
    const float4* __restrict__ in, __half2* __restrict__ out, int n4)
{
    int stride = gridDim.x*256;
    for (int i = blockIdx.x*256 + threadIdx.x; i < n4; i += stride){
        float4 v = in[i];
        out[2*i]   = __floats2half2_rn(v.x, v.y);
        out[2*i+1] = __floats2half2_rn(v.z, v.w);
    }
}
__global__ void __launch_bounds__(256) roundw4_kernel(
    const float4* __restrict__ a, const float4* __restrict__ b,
    const float4* __restrict__ c, const float4* __restrict__ d,
    float4* __restrict__ out, int n4)
{
    int i = blockIdx.x*256 + threadIdx.x;
    if (i >= n4) return;
    const float4* src = (blockIdx.z == 0) ? a : (blockIdx.z == 1) ? b :
                        (blockIdx.z == 2) ? c : d;
    float4 v = src[i];
    v.x = rtf(v.x); v.y = rtf(v.y); v.z = rtf(v.z); v.w = rtf(v.w);
    out[(size_t)blockIdx.z*n4 + i] = v;
}

// ------------------------------------------------------------ rms + gate (+router)
__global__ void __launch_bounds__(256) rms_router_kernel(
    const float* __restrict__ x, const float* __restrict__ nw,
    const float* __restrict__ gw, const float* __restrict__ gb,
    float* __restrict__ y, __half* __restrict__ yh, float* __restrict__ gate,
    const float* __restrict__ rw, const float* __restrict__ rb,
    float* __restrict__ hw)
{
    __shared__ float sy[HDIM];
    __shared__ float wss[8], wgd[8];
    int t = blockIdx.x, tid = threadIdx.x;
    int lane = tid & 31, warp = tid >> 5;
    const float* xr = x + (size_t)t*HDIM;
    float ss = 0.f, gd = 0.f;
    for (int i = tid; i < HDIM; i += 256){
        float v = xr[i]; sy[i] = v; ss += v*v; gd += v*gw[i];
    }
    #pragma unroll
    for (int o = 16; o; o >>= 1){
        ss += __shfl_xor_sync(0xffffffffu, ss, o);
        gd += __shfl_xor_sync(0xffffffffu, gd, o);
    }
    if (lane == 0){ wss[warp] = ss; wgd[warp] = gd; }
    __syncthreads();
    float tot = wss[0]+wss[1]+wss[2]+wss[3]+wss[4]+wss[5]+wss[6]+wss[7];
    float rs = rsqrtf(tot*(1.f/HDIM) + 1e-6f);
    if (tid == 0){
        float tg = wgd[0]+wgd[1]+wgd[2]+wgd[3]+wgd[4]+wgd[5]+wgd[6]+wgd[7];
        gate[t] = sigf(tg + gb[0]);
    }
    for (int i = tid; i < HDIM; i += 256){
        float v = sy[i]*rs*nw[i];
        if (y)  y[(size_t)t*HDIM + i] = v;
        if (yh) yh[(size_t)t*HDIM + i] = __float2half_rn(v);
        sy[i] = v;
    }
    if (rw){
        __syncthreads();
        for (int r = warp; r < NHEADS; r += 8){
            float s = 0.f;
            for (int i = lane; i < HDIM; i += 32) s += sy[i]*rw[r*HDIM + i];
            #pragma unroll
            for (int o = 16; o; o >>= 1) s += __shfl_down_sync(0xffffffffu, s, o);
            if (lane == 0) hw[(size_t)t*NHEADS + r] = sigf(s + rb[r]);
        }
    }
}

// ------------------------------------------------------------ fused 6-stage conv stack
__global__ void __launch_bounds__(256) convfused_kernel(
    const float* __restrict__ in, __half* __restrict__ out,
    const float* __restrict__ w, const float* __restrict__ b)
{
    extern __shared__ float cs[];
    float* buf0 = cs;
    float* buf1 = cs + SL*8;
    int cg = blockIdx.x % (HDIM/8);
    int bb = blockIdx.x / (HDIM/8);
    int c0 = cg*8;
    int tid = threadIdx.x;
    const float* base = in + (size_t)bb*SL*HDIM + c0;
    for (int e = tid; e < SL*8; e += 256){
        int t = e >> 3, c = e & 7;
        buf0[e] = base[(size_t)t*HDIM + c];
    }
    __syncthreads();
    float* src = buf0; float* dst = buf1;
    int c = tid & 7;
    #pragma unroll
    for (int j = 0; j < 6; j++){
        int dil = 1 << j;
        float w0 = w[(j*HDIM + c0 + c)*KW + 0];
        float w1 = w[(j*HDIM + c0 + c)*KW + 1];
        float w2 = w[(j*HDIM + c0 + c)*KW + 2];
        float w3 = w[(j*HDIM + c0 + c)*KW + 3];
        float bj = b[j*HDIM + c0 + c];
        for (int t = tid >> 3; t < SL; t += 32){
            float xv = src[t*8 + c];
            float a = bj + xv*w3;
            int t1 = t - dil, t2 = t - 2*dil, t3 = t - 3*dil;
            if (t1 >= 0) a += src[t1*8 + c]*w2;
            if (t2 >= 0) a += src[t2*8 + c]*w1;
            if (t3 >= 0) a += src[t3*8 + c]*w0;
            dst[t*8 + c] = xv + geluf(a);
        }
        __syncthreads();
        float* tmp = src; src = dst; dst = tmp;
    }
    __half* obase = out + (size_t)bb*SL*HDIM + c0;
    for (int e = tid; e < SL*8; e += 256){
        int t = e >> 3, cc = e & 7;
        obase[(size_t)t*HDIM + cc] = __float2half_rn(src[e]);
    }
}

// ------------------------------------------------------------ fused head conv + mem add + router scale
__global__ void __launch_bounds__(256) headconv_fused(
    const float* __restrict__ xh, const float* __restrict__ mo,
    const float* __restrict__ hwv,
    const float* __restrict__ w, const float* __restrict__ b,
    __half* __restrict__ out)
{
    extern __shared__ float cs[];
    float* buf0 = cs;
    float* buf1 = cs + SL*4;
    int g4   = blockIdx.x & 31;
    int head = (blockIdx.x >> 5) % NHEADS;
    int bb   = blockIdx.x / (32*NHEADS);
    int tid = threadIdx.x;
    int c = tid & 3;
    int ch0 = head*HDH + g4*4;
    const float* base = xh + (size_t)bb*SL*HDIM + ch0;
    for (int e = tid; e < SL*4; e += 256){
        int t = e >> 2, cc = e & 3;
        buf0[e] = base[(size_t)t*HDIM + cc];
    }
    __syncthreads();
    float* src = buf0; float* dst = buf1;
    #pragma unroll
    for (int j = 0; j < 3; j++){
        int dil = c_dils[head][j];
        int d = g4*4 + c;
        const float* wp = w + ((head*3 + j)*HDH + d)*KW;
        float w0 = wp[0], w1 = wp[1], w2 = wp[2], w3 = wp[3];
        float bj = b[(head*3 + j)*HDH + d];
        for (int t = tid >> 2; t < SL; t += 64){
            float xv = src[t*4 + c];
            float a = bj + xv*w3;
            int t1 = t - dil, t2 = t - 2*dil, t3 = t - 3*dil;
            if (t1 >= 0) a += src[t1*4 + c]*w2;
            if (t2 >= 0) a += src[t2*4 + c]*w1;
            if (t3 >= 0) a += src[t3*4 + c]*w0;
            dst[t*4 + c] = xv + a;
        }
        __syncthreads();
        float* tmp = src; src = dst; dst = tmp;
    }
    __half* obase = out + (size_t)bb*SL*HDIM + ch0;
    bool memh = (head >= 6 && head <= 9);
    for (int e = tid; e < SL*4; e += 256){
        int t = e >> 2, cc = e & 3;
        long tok = (long)bb*SL + t;
        float v = src[e];
        if (memh) v += mo[(tok*4 + (head-6))*HDH + g4*4 + cc];
        obase[(size_t)t*HDIM + cc] = __float2half_rn(v * hwv[tok*NHEADS + head]);
    }
}

// ------------------------------------------------------------ GLU + memgate fused (fp16 input)
__global__ void __launch_bounds__(256) glu_gate_h8(
    const uint4* __restrict__ big, float4* __restrict__ xh,
    const float* __restrict__ wg, const float* __restrict__ bg,
    float* __restrict__ gm)
{
    __shared__ float red[8][4];
    int t = blockIdx.x, tid = threadIdx.x;
    int lane = tid & 31, warp = tid >> 5;
    const uint4* crow = big + (size_t)t*(2*HDIM/8);
    const uint4* grow = crow + HDIM/8;
    float4* orow = xh + (size_t)t*(HDIM/4);
    float acc0=0.f, acc1=0.f, acc2=0.f, acc3=0.f;
    for (int i = tid; i < HDIM/8; i += 256){
        uint4 cu = crow[i];
        uint4 gu = grow[i];
        const uint32_t* cp = (const uint32_t*)&cu;
        const uint32_t* gp = (const uint32_t*)&gu;
        float o[8];
        #pragma unroll
        for (int j = 0; j < 4; j++){
            float2 cf = __half22float2(*(const __half2*)&cp[j]);
            float2 gf = __half22float2(*(const __half2*)&gp[j]);
            o[2*j]   = rtf(cf.x*sigf(gf.x));
            o[2*j+1] = rtf(cf.y*sigf(gf.y));
        }
        float4 o0, o1;
        o0.x=o[0]; o0.y=o[1]; o0.z=o[2]; o0.w=o[3];
        o1.x=o[4]; o1.y=o[5]; o1.z=o[6]; o1.w=o[7];
        orow[2*i]   = o0;
        orow[2*i+1] = o1;
        int ch = i*8;
        if (ch >= 6*HDH && ch < 10*HDH){
            int h = (ch - 6*HDH) >> 7;
            int d = (ch - 6*HDH) & 127;
            const float* wp = wg + h*HDH + d;
            float s = 0.f;
            #pragma unroll
            for (int j = 0; j < 8; j++) s += o[j]*wp[j];
            if (h == 0) acc0 += s; else if (h == 1) acc1 += s;
            else if (h == 2) acc2 += s; else acc3 += s;
        }
    }
    #pragma unroll
    for (int o = 16; o; o >>= 1){
        acc0 += __shfl_xor_sync(0xffffffffu, acc0, o);
        acc1 += __shfl_xor_sync(0xffffffffu, acc1, o);
        acc2 += __shfl_xor_sync(0xffffffffu, acc2, o);
        acc3 += __shfl_xor_sync(0xffffffffu, acc3, o);
    }
    if (lane == 0){
        red[warp][0] = acc0; red[warp][1] = acc1;
        red[warp][2] = acc2; red[warp][3] = acc3;
    }
    __syncthreads();
    if (tid < 4){
        float s = 0.f;
        #pragma unroll
        for (int w2 = 0; w2 < 8; w2++) s += red[w2][tid];
        gm[t*4 + tid] = sigf(s + bg[tid]);
    }
}

// ------------------------------------------------------------ fp16 GLU (FFN)
__global__ void __launch_bounds__(256) glu_h8(
    const uint4* __restrict__ big, uint4* __restrict__ out, int N8)
{
    long idx = (long)blockIdx.x*256 + threadIdx.x;
    if (idx >= (long)NT*N8) return;
    long m = idx / N8; int n = (int)(idx % N8);
    uint4 cu = big[m*2*N8 + n];
    uint4 gu = big[m*2*N8 + N8 + n];
    uint4 ou;
    uint32_t* cp = (uint32_t*)&cu;
    uint32_t* gp = (uint32_t*)&gu;
    uint32_t* op = (uint32_t*)&ou;
    #pragma unroll
    for (int j = 0; j < 4; j++){
        float2 cf = __half22float2(*(__half2*)&cp[j]);
        float2 gf = __half22float2(*(__half2*)&gp[j]);
        __half2 r = __floats2half2_rn(cf.x*sigf(gf.x), cf.y*sigf(gf.y));
        op[j] = *(uint32_t*)&r;
    }
    out[idx] = ou;
}

// ------------------------------------------------------------ memory scan
#define SCAN_SMEM ((64*QS*2 + 64*MT + 64 + 128*(MT+1) + 4)*4)
__global__ void __launch_bounds__(256) memscan_kernel(
    const float* __restrict__ q, const float* __restrict__ k,
    const float* __restrict__ v, const float* __restrict__ g,
    float* __restrict__ reads)
{
    extern __shared__ float smem[];
    float* sQ  = smem;
    float* sK  = sQ + 64*QS;
    float* sV  = sK + 64*QS;
    float* sG  = sV + 64*MT;
    float* sM  = sG + 64;
    float* sDec= sM + 128*(MT+1);
    int tid  = threadIdx.x;
    int mblk = blockIdx.x & 15;
    int h    = (blockIdx.x >> 4) & 3;
    int b    = blockIdx.x >> 6;
    int m0   = mblk * MT;
    for (int i = tid; i < 128*(MT+1); i += 256) sM[i] = 0.f;
    for (int c = 0; c < NCHUNK; c++){
        int tok0 = b*SL + c*CHUNK;
        __syncthreads();
        if (tid < 64) sG[tid] = g[(tok0 + tid)*4 + h];
        __syncthreads();
        #pragma unroll
        for (int it = 0; it < 8; it++){
            int li = tid + it*256;
            int s  = li >> 5;
            int e4 = (li & 31) << 2;
            size_t gi = ((size_t)(tok0 + s)*4 + h)*HDH + e4;
            float4 qa = *(const float4*)(q + gi);
            float4 ka = *(const float4*)(k + gi);
            float gs = sG[s];
            int so = s*QS + e4;
            sQ[so] = qa.x; sQ[so+1] = qa.y; sQ[so+2] = qa.z; sQ[so+3] = qa.w;
            sK[so] = ka.x*gs; sK[so+1] = ka.y*gs; sK[so+2] = ka.z*gs; sK[so+3] = ka.w*gs;
        }
        if (tid < 128){
            int s = tid >> 1; int mm = (tid & 1)*4;
            float4 va = *(const float4*)(v + ((size_t)(tok0 + s)*4 + h)*HDH + m0 + mm);
            float* dv = &sV[s*MT + mm];
            dv[0]=va.x; dv[1]=va.y; dv[2]=va.z; dv[3]=va.w;
        }
        __syncthreads();
        if (tid < 32){
            float dsum = sG[tid] + sG[tid + 32];
            #pragma unroll
            for (int o = 16; o; o >>= 1) dsum += __shfl_down_sync(0xffffffffu, dsum, o);
            if (tid == 0) sDec[0] = 1.f - dsum*(1.f/64.f);
        }
        {
            int s  = tid & 63;
            int mi = (tid >> 6)*2;
            float a0 = 0.f, a1 = 0.f;
            const float* qr = sQ + s*QS;
            #pragma unroll 8
            for (int d = 0; d < HDH; d++){
                float qv = qr[d];
                a0 += qv * sM[d*(MT+1) + mi];
                a1 += qv * sM[d*(MT+1) + mi + 1];
            }
            size_t ro = ((size_t)(tok0 + s)*4 + h)*HDH + m0 + mi;
            reads[ro] = rtf(a0); reads[ro+1] = rtf(a1);
        }
        __syncthreads();
        {
            int d  = tid & 127;
            int mb = (tid >> 7)*4;
            float dec = sDec[0];
            float a0 = dec*sM[d*(MT+1)+mb+0];
            float a1 = dec*sM[d*(MT+1)+mb+1];
            float a2 = dec*sM[d*(MT+1)+mb+2];
            float a3 = dec*sM[d*(MT+1)+mb+3];
            #pragma unroll 8
            for (int s = 0; s < 64; s++){
                float kgv = sK[s*QS + d];
                const float* vr = sV + s*MT + mb;
                a0 += kgv*vr[0]; a1 += kgv*vr[1]; a2 += kgv*vr[2]; a3 += kgv*vr[3];
            }
            sM[d*(MT+1)+mb+0]=a0; sM[d*(MT+1)+mb+1]=a1;
            sM[d*(MT+1)+mb+2]=a2; sM[d*(MT+1)+mb+3]=a3;
        }
    }
}

// ------------------------------------------------------------ host side
template<typename T>
static T* F(const void* sym){
    void* p = nullptr;
    cudaGetSymbolAddress(&p, sym);
    return (T*)p;
}

#define GEMMH_SMEM (3*H2STAGE*4)
#define CONV_SMEM  (2*SL*8*4)
#define HC_SMEM    (2*SL*4*4)

static void gemmH(const __half* A, const __half* W, void* C,
                  long lda, long ldw, long ldc, int M, int N, int K,
                  int epi, int outH, const float* bias,
                  const float* resid, const float* gate)
{
    dim3 g(N/128, M/128, 1);
    mma_gemm_h<<<g, 256, GEMMH_SMEM>>>(A, lda, W, ldw, C, ldc,
                                       K, epi, outH, bias, resid, gate);
}
static void cvtwS(const float* in, __half* out, size_t n, cudaStream_t st){
    int n4 = (int)(n/4);
    int grid = (n4/4 + 255)/256;
    if (grid < 1) grid = 1;
    cvtw_kernel<<<grid, 256, 0, st>>>((const float4*)in, (__half2*)out, n4);
}

extern "C" void kernel_launch(void* const* d_in, const int* in_sizes, int n_in,
                              void* d_out, int out_size)
{
    const float* x            = (const float*)d_in[0];
    const float* norm1_w      = (const float*)d_in[1];
    const float* norm2_w      = (const float*)d_in[2];
    const float* norm3_w      = (const float*)d_in[3];
    const float* convstack_w  = (const float*)d_in[4];
    const float* convstack_b  = (const float*)d_in[5];
    const float* conv_proj_w  = (const float*)d_in[6];
    const float* conv_proj_b  = (const float*)d_in[7];
    const float* gate_proj_w  = (const float*)d_in[8];
    const float* head_router_w= (const float*)d_in[9];
    const float* head_router_b= (const float*)d_in[10];
    const float* head_conv_w  = (const float*)d_in[11];
    const float* head_conv_b  = (const float*)d_in[12];
    const float* mem_Wq       = (const float*)d_in[13];
    const float* mem_Wk       = (const float*)d_in[14];
    const float* mem_Wv       = (const float*)d_in[15];
    const float* mem_Wg_w     = (const float*)d_in[16];
    const float* mem_Wg_b     = (const float*)d_in[17];
    const float* mem_Wout     = (const float*)d_in[18];
    const float* mix_gate_w   = (const float*)d_in[19];
    const float* mix_gate_b   = (const float*)d_in[20];
    const float* mixing_w     = (const float*)d_in[21];
    const float* mixing_b     = (const float*)d_in[22];
    const float* ffn_in_w     = (const float*)d_in[23];
    const float* ffn_out_w    = (const float*)d_in[24];
    const float* conv_gate_w  = (const float*)d_in[25];
    const float* conv_gate_b  = (const float*)d_in[26];
    const float* state_gate_w = (const float*)d_in[27];
    const float* state_gate_b = (const float*)d_in[28];
    const float* ffn_gate_w   = (const float*)d_in[29];
    const float* ffn_gate_b   = (const float*)d_in[30];
    float* out = (float*)d_out;

    float*  y    = F<float>(g_y);
    float*  xh   = F<float>(g_xh);
    float*  qb   = F<float>(g_q);
    float*  kb   = F<float>(g_k);
    float*  vb   = F<float>(g_v);
    float*  rd   = F<float>(g_rd);
    float*  mo   = F<float>(g_mo);
    float*  gm   = F<float>(g_gm);
    float*  hw   = F<float>(g_hw);
    float*  gate = F<float>(g_gate);
    float*  wr   = F<float>(g_wr);
    __half* hy   = F<__half>(g_hy);
    __half* ht0  = F<__half>(g_ht0);
    __half* htc  = F<__half>(g_htc);
    __half* ht1  = F<__half>(g_ht1);
    __half* hffn = F<__half>(g_hffn);
    __half* hbig = F<__half>(g_hbig);
    __half* hwt  = F<__half>(g_hwt);

    __half* hw_cp = hwt;                // conv_proj  2359296
    __half* hw_gp = hwt + 2359296;      // gate_proj  4718592
    __half* hw_mg = hwt + 7077888;      // mix_gate   2359296
    __half* hw_mx = hwt + 9437184;      // mixing     2359296
    __half* hw_fi = hwt + 11796480;     // ffn_in    18874368
    __half* hw_fo = hwt + 30670848;     // ffn_out    9437184
    float* w_q = wr;                    // [wq|wk|wv|wo] each 65536

    cudaFuncSetAttribute(memscan_kernel,
        cudaFuncAttributeMaxDynamicSharedMemorySize, SCAN_SMEM);
    cudaFuncSetAttribute(mma_gemm_h,
        cudaFuncAttributeMaxDynamicSharedMemorySize, GEMMH_SMEM);
    cudaFuncSetAttribute(convfused_kernel,
        cudaFuncAttributeMaxDynamicSharedMemorySize, CONV_SMEM);
    cudaFuncSetAttribute(headconv_fused,
        cudaFuncAttributeMaxDynamicSharedMemorySize, HC_SMEM);

    static cudaStream_t s2 = nullptr;
    static cudaEvent_t evF = nullptr, evJ = nullptr;
    if (!s2){
        cudaStreamCreateWithFlags(&s2, cudaStreamNonBlocking);
        cudaEventCreateWithFlags(&evF, cudaEventDisableTiming);
        cudaEventCreateWithFlags(&evJ, cudaEventDisableTiming);
    }

    // fork: weight prep for stages B/C overlaps stage A
    cudaEventRecord(evF, 0);
    cudaStreamWaitEvent(s2, evF, 0);
    cvtwS(gate_proj_w, hw_gp, 4718592, s2);
    cvtwS(mix_gate_w,  hw_mg, 2359296, s2);
    cvtwS(mixing_w,  hw_mx, 2359296, s2);
    cvtwS(ffn_in_w,  hw_fi, 18874368, s2);
    cvtwS(ffn_out_w, hw_fo, 9437184, s2);
    roundw4_kernel<<<dim3(64,1,4), 256, 0, s2>>>(
        (const float4*)mem_Wq, (const float4*)mem_Wk,
        (const float4*)mem_Wv, (const float4*)mem_Wout,
        (float4*)w_q, 16384);
    cudaEventRecord(evJ, s2);

    // ============ stage A ============
    cvtwS(conv_proj_w, hw_cp, 2359296, 0);
    rms_router_kernel<<<NT,256>>>(x, norm1_w, conv_gate_w, conv_gate_b,
                                  y, nullptr, gate, nullptr, nullptr, nullptr);
    convfused_kernel<<<BB*(HDIM/8), 256, CONV_SMEM>>>(y, ht0,
                                  convstack_w, convstack_b);
    gemmH(ht0, hw_cp, out, HDIM, HDIM, HDIM, NT, HDIM, HDIM, 1, 0,
          conv_proj_b, x, gate);

    cudaStreamWaitEvent(0, evJ, 0);

    // ============ stage B: state branch ============
    rms_router_kernel<<<NT,256>>>(out, norm2_w, state_gate_w, state_gate_b,
                                  nullptr, hy, gate, head_router_w, head_router_b, hw);
    gemmH(hy, hw_gp, hbig, HDIM, HDIM, 2*HDIM, NT, 2*HDIM, HDIM, 0, 1,
          nullptr, nullptr, nullptr);
    glu_gate_h8<<<NT,256>>>((const uint4*)hbig, (float4*)xh,
                            mem_Wg_w, mem_Wg_b, gm);
    {
        dim3 g(1, NT/128, 12);
        mma_gemm_qkv<<<g, 256>>>(xh + 6*HDH, HDIM, HDH, w_q, qb, kb, vb, 128);
    }
    memscan_kernel<<<BB*4*(MEMD/MT), 256, SCAN_SMEM>>>(qb, kb, vb, gm, rd);
    {
        dim3 g(1, NT/128, 4);
        mma_gemm_small<<<g, 256>>>(rd, 512, HDH, w_q + 196608, 16384, mo, HDH, 128);
    }
    headconv_fused<<<BB*NHEADS*32, 256, HC_SMEM>>>(xh, mo, hw,
                                  head_conv_w, head_conv_b, htc);
    gemmH(htc, hw_mg, ht1, HDIM, HDIM, HDIM, NT, HDIM, HDIM, 2, 1,
          mix_gate_b, nullptr, nullptr);
    gemmH(ht1, hw_mx, out, HDIM, HDIM, HDIM, NT, HDIM, HDIM, 1, 0,
          mixing_b, out, gate);

    // ============ stage C: FFN ============
    rms_router_kernel<<<NT,256>>>(out, norm3_w, ffn_gate_w, ffn_gate_b,
                                  nullptr, hy, gate, nullptr, nullptr, nullptr);
    gemmH(hy, hw_fi, hbig, HDIM, HDIM, 2*INNERD, NT, 2*INNERD, HDIM, 0, 1,
          nullptr, nullptr, nullptr);
    glu_h8<<<(NT*(INNERD/8) + 255)/256, 256>>>((const uint4*)hbig, (uint4*)hffn, INNERD/8);
    gemmH(hffn, hw_fo, out, INNERD, INNERD, HDIM, NT, HDIM, INNERD, 1, 0,
          nullptr, out, gate);
}